// round 6
// baseline (speedup 1.0000x reference)
#include <cuda_runtime.h>
#include <cuda_bf16.h>
#include <cstdint>

// word_vecs [B=2048, S=200, D=300] fp32 -> masked mean over S -> [B, D].
// All-zero words contribute 0 to the sum, so only the COUNT needs the mask.
//
// 256-bit load variant: process WORD PAIRS (600 floats = 75 float8), so all 75
// active lanes issue one 32B-aligned ld.global.nc.v8.f32 per pair -> half the
// load instructions of the float4 version at identical bytes-in-flight
// (unroll 2 x 32B == unroll 4 x 16B). Thread 37 straddles the word boundary;
// even/odd words map dims to different threads, so accumulators are realigned
// once per CTA via a small shared staging buffer.

#define B_DIM 2048
#define S_DIM 200
#define PAIRS 100
#define VDIM  75        // active threads
#define NTHREADS 96
#define SENT_FLOATS (S_DIM * 300)   // 60000 floats per sentence

__global__ __launch_bounds__(NTHREADS)
void sentence_rep_kernel(const float* __restrict__ in, float4* __restrict__ out) {
    __shared__ unsigned char flags[S_DIM];
    __shared__ float sh[600];       // flat even|odd accumulator staging
    __shared__ float inv_count;

    const int b = blockIdx.x;
    const int t = threadIdx.x;
    const int lane = t & 31;
    const int wid = t >> 5;
    const bool active = (t < VDIM);

    for (int i = t; i < S_DIM; i += NTHREADS) flags[i] = 0;
    __syncthreads();

    const float* __restrict__ p = in + (size_t)b * SENT_FLOATS + 8 * t;

    float a0 = 0.f, a1 = 0.f, a2 = 0.f, a3 = 0.f;
    float a4 = 0.f, a5 = 0.f, a6 = 0.f, a7 = 0.f;

    #pragma unroll 2
    for (int q = 0; q < PAIRS; ++q) {
        float v0 = 0.f, v1 = 0.f, v2 = 0.f, v3 = 0.f;
        float v4 = 0.f, v5 = 0.f, v6 = 0.f, v7 = 0.f;
        if (active) {
            asm("ld.global.nc.v8.f32 {%0,%1,%2,%3,%4,%5,%6,%7}, [%8];"
                : "=f"(v0), "=f"(v1), "=f"(v2), "=f"(v3),
                  "=f"(v4), "=f"(v5), "=f"(v6), "=f"(v7)
                : "l"(p + q * 600));
        }
        a0 += v0; a1 += v1; a2 += v2; a3 += v3;
        a4 += v4; a5 += v5; a6 += v6; a7 += v7;

        // nonzero tests (sign bit cleared: -0.0f padding counts as zero)
        unsigned lo = (__float_as_uint(v0) | __float_as_uint(v1) |
                       __float_as_uint(v2) | __float_as_uint(v3)) & 0x7fffffffu;
        unsigned hi = (__float_as_uint(v4) | __float_as_uint(v5) |
                       __float_as_uint(v6) | __float_as_uint(v7)) & 0x7fffffffu;
        bool nzl = (lo != 0u), nzh = (hi != 0u);

        // thread t covers flats [8t, 8t+8): t<37 -> even word; t==37 -> split
        // (first 4 even word, last 4 odd word); t>37 -> odd word.
        if (wid == 0) {                       // t 0..31: even word only
            unsigned m0 = __ballot_sync(0xffffffffu, nzl || nzh);
            if (lane == 0 && m0) flags[2 * q] = 1;
        } else if (wid == 1) {                // t 32..63: both words
            bool nz_even = (t < 37) ? (nzl || nzh) : (t == 37 ? nzl : false);
            bool nz_odd  = (t < 37) ? false       : (t == 37 ? nzh : (nzl || nzh));
            unsigned m0 = __ballot_sync(0xffffffffu, nz_even);
            unsigned m1 = __ballot_sync(0xffffffffu, nz_odd);
            if (lane == 0) {
                if (m0) flags[2 * q] = 1;
                if (m1) flags[2 * q + 1] = 1;
            }
        } else {                              // t 64..95 (active <75): odd word
            unsigned m1 = __ballot_sync(0xffffffffu, active && (nzl || nzh));
            if (lane == 0 && m1) flags[2 * q + 1] = 1;
        }
    }

    // stage flat accumulators for even/odd realignment
    if (active) {
        sh[8 * t + 0] = a0; sh[8 * t + 1] = a1; sh[8 * t + 2] = a2; sh[8 * t + 3] = a3;
        sh[8 * t + 4] = a4; sh[8 * t + 5] = a5; sh[8 * t + 6] = a6; sh[8 * t + 7] = a7;
    }
    __syncthreads();

    if (t < 32) {
        int c = 0;
        for (int i = t; i < S_DIM; i += 32) c += (int)flags[i];
        #pragma unroll
        for (int o = 16; o > 0; o >>= 1) c += __shfl_down_sync(0xffffffffu, c, o);
        if (t == 0) inv_count = 1.0f / (float)c;   // count >= 1 guaranteed
    }
    __syncthreads();

    if (active) {
        const float ic = inv_count;
        const int d = 4 * t;                    // dims 4t..4t+3
        float4 r;
        r.x = (sh[d + 0] + sh[300 + d + 0]) * ic;
        r.y = (sh[d + 1] + sh[300 + d + 1]) * ic;
        r.z = (sh[d + 2] + sh[300 + d + 2]) * ic;
        r.w = (sh[d + 3] + sh[300 + d + 3]) * ic;
        out[(size_t)b * VDIM + t] = r;
    }
}

extern "C" void kernel_launch(void* const* d_in, const int* in_sizes, int n_in,
                              void* d_out, int out_size) {
    (void)in_sizes; (void)n_in; (void)out_size;
    const float* in = (const float*)d_in[0];
    float4* out = (float4*)d_out;
    sentence_rep_kernel<<<B_DIM, NTHREADS>>>(in, out);
}

// round 7
// speedup vs baseline: 1.1173x; 1.1173x over previous
#include <cuda_runtime.h>
#include <cuda_bf16.h>

// word_vecs [B=2048, S=200, D=300] fp32 -> masked mean over S -> [B, D].
// A masked (all-zero) word contributes 0 to the sum, so the sum needs no mask;
// only the count does. Byte-identical load stream to the 77.7us R5 winner
// (float4, unroll 4, __ldcs, per-word pacing); the per-word __ballot_sync is
// replaced by a directly predicated same-value shared store (multi-lane
// same-address STS collapses; benign race), removing 200 warp-reconvergence
// points per thread without touching the load pacing.

#define B_DIM 2048
#define S_DIM 200
#define VDIM  75   // 300 floats = 75 float4 per word (1200 B, 16B-aligned)
#define NTHREADS 96

__global__ __launch_bounds__(NTHREADS)
void sentence_rep_kernel(const float4* __restrict__ in, float4* __restrict__ out) {
    __shared__ unsigned char flags[S_DIM];
    __shared__ float inv_count;

    const int b = blockIdx.x;
    const int t = threadIdx.x;
    const bool active = (t < VDIM);

    for (int i = t; i < S_DIM; i += NTHREADS) flags[i] = 0;
    __syncthreads();

    const float4* __restrict__ row = in + (size_t)b * (S_DIM * VDIM);

    float4 acc = make_float4(0.f, 0.f, 0.f, 0.f);

    #pragma unroll 4
    for (int s = 0; s < S_DIM; ++s) {
        float4 v = make_float4(0.f, 0.f, 0.f, 0.f);
        if (active) v = __ldcs(&row[s * VDIM + t]);
        acc.x += v.x; acc.y += v.y; acc.z += v.z; acc.w += v.w;

        // any-nonzero -> flag. Multiple lanes may store the same byte value to
        // the same smem address; the write collapses (benign race, no ballot).
        bool nz = (v.x != 0.f) || (v.y != 0.f) || (v.z != 0.f) || (v.w != 0.f);
        if (nz) flags[s] = 1;
    }
    __syncthreads();

    if (t < 32) {
        int c = 0;
        for (int i = t; i < S_DIM; i += 32) c += (int)flags[i];
        #pragma unroll
        for (int o = 16; o > 0; o >>= 1) c += __shfl_down_sync(0xffffffffu, c, o);
        if (t == 0) inv_count = 1.0f / (float)c;   // count >= 1 guaranteed
    }
    __syncthreads();

    if (active) {
        const float ic = inv_count;
        out[(size_t)b * VDIM + t] =
            make_float4(acc.x * ic, acc.y * ic, acc.z * ic, acc.w * ic);
    }
}

extern "C" void kernel_launch(void* const* d_in, const int* in_sizes, int n_in,
                              void* d_out, int out_size) {
    (void)in_sizes; (void)n_in; (void)out_size;
    const float4* in = (const float4*)d_in[0];
    float4* out = (float4*)d_out;
    sentence_rep_kernel<<<B_DIM, NTHREADS>>>(in, out);
}